// round 6
// baseline (speedup 1.0000x reference)
#include <cuda_runtime.h>
#include <cuda_bf16.h>
#include <math.h>
#include <stdint.h>

#define B_    2
#define T_    2048
#define C_    2048
#define H_    16
#define HKV_  4
#define HD_   128
#define KVD_  512
#define QKVN_ 3072
#define EPS_  1.1920929e-07f
#define M_ROWS (B_ * T_)     // 4096
#define SCALE_ 0.08838834764831845f

// ---------------- scratch -----------------------------------------------------
__device__ __nv_bfloat16 g_ah[(size_t)M_ROWS * C_];   // A hi (rmsnorm(x), later attn out)
__device__ __nv_bfloat16 g_al[(size_t)M_ROWS * C_];   // A lo
__device__ __nv_bfloat16 g_bh1[(size_t)QKVN_ * C_];   // w_qkv^T hi  [N,K]
__device__ __nv_bfloat16 g_bl1[(size_t)QKVN_ * C_];
__device__ __nv_bfloat16 g_bh2[(size_t)C_ * C_];      // w_proj^T hi [N,K]
__device__ __nv_bfloat16 g_bl2[(size_t)C_ * C_];
__device__ float g_qkv[(size_t)M_ROWS * QKVN_];
__device__ __nv_bfloat16 g_qh[(size_t)B_ * H_ * T_ * HD_];
__device__ __nv_bfloat16 g_ql[(size_t)B_ * H_ * T_ * HD_];
__device__ __nv_bfloat16 g_kh[(size_t)B_ * HKV_ * T_ * HD_];
__device__ __nv_bfloat16 g_kl[(size_t)B_ * HKV_ * T_ * HD_];
__device__ __nv_bfloat16 g_vth[(size_t)B_ * HKV_ * HD_ * T_];  // [b,g][hd][t]
__device__ __nv_bfloat16 g_vtl[(size_t)B_ * HKV_ * HD_ * T_];
__device__ float g_cos[T_ * 64];
__device__ float g_sin[T_ * 64];

// ---------------- PTX helpers ---------------------------------------------------
__device__ __forceinline__ uint32_t smem_u32(const void* p) {
    uint32_t a;
    asm("{ .reg .u64 t; cvta.to.shared.u64 t, %1; cvt.u32.u64 %0, t; }" : "=r"(a) : "l"(p));
    return a;
}
__device__ __forceinline__ void cpa16(uint32_t dst, const void* src) {
    asm volatile("cp.async.cg.shared.global [%0], [%1], 16;" :: "r"(dst), "l"(src) : "memory");
}
__device__ __forceinline__ void cpa_commit() { asm volatile("cp.async.commit_group;" ::: "memory"); }
__device__ __forceinline__ void cpa_wait0()  { asm volatile("cp.async.wait_group 0;" ::: "memory"); }
__device__ __forceinline__ void cpa_wait1()  { asm volatile("cp.async.wait_group 1;" ::: "memory"); }

__device__ __forceinline__ void ldm_x4(uint32_t* r, uint32_t addr) {
    asm volatile("ldmatrix.sync.aligned.m8n8.x4.shared.b16 {%0,%1,%2,%3}, [%4];"
                 : "=r"(r[0]), "=r"(r[1]), "=r"(r[2]), "=r"(r[3]) : "r"(addr));
}
__device__ __forceinline__ void mma_bf16(float* c, const uint32_t* a, const uint32_t* b) {
    asm volatile(
        "mma.sync.aligned.m16n8k16.row.col.f32.bf16.bf16.f32 "
        "{%0,%1,%2,%3},{%4,%5,%6,%7},{%8,%9},{%0,%1,%2,%3};"
        : "+f"(c[0]), "+f"(c[1]), "+f"(c[2]), "+f"(c[3])
        : "r"(a[0]), "r"(a[1]), "r"(a[2]), "r"(a[3]), "r"(b[0]), "r"(b[1]));
}
__device__ __forceinline__ void bsplit(float v, __nv_bfloat16& h, __nv_bfloat16& l) {
    h = __float2bfloat16(v);
    l = __float2bfloat16(v - __bfloat162float(h));
}

// ---------------- RoPE tables ---------------------------------------------------
__global__ void k_rope() {
    int t = blockIdx.x;
    int j = threadIdx.x;
    float invf = 1.0f / powf(10000.0f, (2.0f * (float)j) / 128.0f);
    float ang = (float)t * invf;
    g_cos[t * 64 + j] = (float)cos((double)ang);
    g_sin[t * 64 + j] = (float)sin((double)ang);
}

// ---------------- input RMSNorm -> bf16 hi/lo split -------------------------------
__global__ void __launch_bounds__(256) k_rmsnorm(const float* __restrict__ x) {
    int row = blockIdx.x;
    const float* xr = x + (size_t)row * C_;
    float ss = 0.f;
    for (int i = threadIdx.x; i < C_; i += 256) { float v = xr[i]; ss = fmaf(v, v, ss); }
    __shared__ float sh[8];
    int lane = threadIdx.x & 31, wid = threadIdx.x >> 5;
#pragma unroll
    for (int o = 16; o; o >>= 1) ss += __shfl_xor_sync(0xffffffffu, ss, o);
    if (lane == 0) sh[wid] = ss;
    __syncthreads();
    float tot = (threadIdx.x < 8) ? sh[threadIdx.x] : 0.f;
    if (wid == 0) {
#pragma unroll
        for (int o = 16; o; o >>= 1) tot += __shfl_xor_sync(0xffffffffu, tot, o);
    }
    __shared__ float sb;
    if (threadIdx.x == 0) sb = tot;
    __syncthreads();
    float sc = rsqrtf(sb * (1.0f / C_) + EPS_);
    for (int i = threadIdx.x; i < C_; i += 256) {
        float v = xr[i] * sc;
        __nv_bfloat16 h, l;
        bsplit(v, h, l);
        g_ah[(size_t)row * C_ + i] = h;
        g_al[(size_t)row * C_ + i] = l;
    }
}

// ---------------- W[K,N] -> W^T[N,K] bf16 hi/lo split -----------------------------
__global__ void __launch_bounds__(256) k_splitw(const float* __restrict__ W,
                                                __nv_bfloat16* __restrict__ Bh,
                                                __nv_bfloat16* __restrict__ Bl,
                                                int K, int N) {
    __shared__ float ts[32][33];
    int nb = blockIdx.x * 32, kb = blockIdx.y * 32;
    int tx = threadIdx.x & 31, ty = threadIdx.x >> 5;
#pragma unroll
    for (int r = ty; r < 32; r += 8)
        ts[r][tx] = W[(size_t)(kb + r) * N + nb + tx];
    __syncthreads();
#pragma unroll
    for (int r = ty; r < 32; r += 8) {
        float v = ts[tx][r];
        __nv_bfloat16 h, l;
        bsplit(v, h, l);
        size_t o = (size_t)(nb + r) * K + kb + tx;
        Bh[o] = h;
        Bl[o] = l;
    }
}

// ---------------- bf16-split mma.sync GEMM: 128x256 block, 64x64 warp tiles --------
#define TSTRIDE 80
#define A_TILE (128 * TSTRIDE)              // 10240
#define B_TILE (256 * TSTRIDE)              // 20480
#define STAGE_BYTES (2 * A_TILE + 2 * B_TILE)   // 61440
#define GSMEM (2 * STAGE_BYTES)             // 122880

__global__ void __launch_bounds__(256) k_gemm_bf16(const __nv_bfloat16* __restrict__ Ah,
                                                   const __nv_bfloat16* __restrict__ Al,
                                                   const __nv_bfloat16* __restrict__ Bh,
                                                   const __nv_bfloat16* __restrict__ Bl,
                                                   float* __restrict__ Cm,
                                                   int M, int N, int K) {
    extern __shared__ char smraw[];
    uint32_t sb = smem_u32(smraw);

    int tid = threadIdx.x;
    int wid = tid >> 5, lane = tid & 31;
    int warp_m = wid & 1, warp_n = wid >> 1;       // 2 x 4
    int m0 = blockIdx.y * 128, n0 = blockIdx.x * 256;
    int NIT = K >> 5;

    auto load_stage = [&](int it, int buf) {
        int k0 = it << 5;
        uint32_t dst0 = sb + buf * STAGE_BYTES;
#pragma unroll
        for (int s = 0; s < 12; s++) {
            int c = tid + s * 256;                  // 0..3071
            if (c < 1024) {                          // A: hi then lo
                int t = c >> 9;
                int cw = c & 511;
                int row = cw >> 2, q = cw & 3;
                const __nv_bfloat16* src = (t ? Al : Ah) + (size_t)(m0 + row) * K + k0 + q * 8;
                cpa16(dst0 + t * A_TILE + row * TSTRIDE + q * 16, src);
            } else {                                  // B: hi then lo
                int cb = c - 1024;
                int t = cb >> 10;
                int cw = cb & 1023;
                int row = cw >> 2, q = cw & 3;
                const __nv_bfloat16* src = (t ? Bl : Bh) + (size_t)(n0 + row) * K + k0 + q * 8;
                cpa16(dst0 + 2 * A_TILE + t * B_TILE + row * TSTRIDE + q * 16, src);
            }
        }
    };

    float acc[4][8][4] = {};
    uint32_t a_off = (uint32_t)(warp_m * 64 + (lane & 15)) * TSTRIDE + ((lane >> 4) << 4);
    uint32_t b_off = (uint32_t)(warp_n * 64 + (lane & 7) + ((lane & 16) >> 1)) * TSTRIDE
                   + ((lane & 8) << 1);

    load_stage(0, 0);
    cpa_commit();

    for (int it = 0; it < NIT; it++) {
        int buf = it & 1;
        if (it + 1 < NIT) {
            load_stage(it + 1, buf ^ 1);
            cpa_commit();
            cpa_wait1();
        } else {
            cpa_wait0();
        }
        __syncthreads();

        uint32_t stg = sb + buf * STAGE_BYTES;
        uint32_t aH = stg + a_off;
        uint32_t aL = stg + A_TILE + a_off;
        uint32_t bH = stg + 2 * A_TILE + b_off;
        uint32_t bL = stg + 2 * A_TILE + B_TILE + b_off;

#pragma unroll
        for (int ks = 0; ks < 2; ks++) {
            uint32_t ko = ks * 32;
            uint32_t ah[4][4], al[4][4];
#pragma unroll
            for (int mt = 0; mt < 4; mt++) {
                ldm_x4(ah[mt], aH + ko + mt * 16 * TSTRIDE);
                ldm_x4(al[mt], aL + ko + mt * 16 * TSTRIDE);
            }
#pragma unroll
            for (int bp = 0; bp < 4; bp++) {
                uint32_t bh4[4], bl4[4];
                ldm_x4(bh4, bH + ko + bp * 16 * TSTRIDE);
                ldm_x4(bl4, bL + ko + bp * 16 * TSTRIDE);
#pragma unroll
                for (int mt = 0; mt < 4; mt++) {
                    mma_bf16(acc[mt][2 * bp],     ah[mt], bh4);
                    mma_bf16(acc[mt][2 * bp],     ah[mt], bl4);
                    mma_bf16(acc[mt][2 * bp],     al[mt], bh4);
                    mma_bf16(acc[mt][2 * bp + 1], ah[mt], bh4 + 2);
                    mma_bf16(acc[mt][2 * bp + 1], ah[mt], bl4 + 2);
                    mma_bf16(acc[mt][2 * bp + 1], al[mt], bh4 + 2);
                }
            }
        }
        __syncthreads();
    }

    int gid = lane >> 2, tg = lane & 3;
#pragma unroll
    for (int mt = 0; mt < 4; mt++) {
#pragma unroll
        for (int nt = 0; nt < 8; nt++) {
            int row = m0 + warp_m * 64 + mt * 16 + gid;
            int col = n0 + warp_n * 64 + nt * 8 + tg * 2;
            *(float2*)(Cm + (size_t)row * N + col) =
                make_float2(acc[mt][nt][0], acc[mt][nt][1]);
            *(float2*)(Cm + (size_t)(row + 8) * N + col) =
                make_float2(acc[mt][nt][2], acc[mt][nt][3]);
        }
    }
}

// ---------------- Q/K rmsnorm + RoPE + gain*scale -> bf16 hi/lo ---------------------
__global__ void __launch_bounds__(256) k_qkpost(const float* __restrict__ qg) {
    int gwarp = (blockIdx.x * 256 + threadIdx.x) >> 5;
    int lane = threadIdx.x & 31;
    const int NQ = B_ * T_ * H_;
    const int NK = B_ * T_ * HKV_;
    if (gwarp < NQ) {
        int h = gwarp % H_;
        int bt = gwarp / H_;
        int t = bt % T_, b = bt / T_;
        const float* src = g_qkv + (size_t)bt * QKVN_ + h * HD_;
        float v0 = src[lane], v1 = src[lane + 32], v2 = src[lane + 64], v3 = src[lane + 96];
        float ss = v0 * v0 + v1 * v1 + v2 * v2 + v3 * v3;
#pragma unroll
        for (int o = 16; o; o >>= 1) ss += __shfl_xor_sync(0xffffffffu, ss, o);
        float sc = rsqrtf(ss * (1.0f / HD_) + EPS_);
        v0 *= sc; v1 *= sc; v2 *= sc; v3 *= sc;
        float c0 = g_cos[t * 64 + lane],      s0 = g_sin[t * 64 + lane];
        float c1 = g_cos[t * 64 + 32 + lane], s1 = g_sin[t * 64 + 32 + lane];
        float gn = qg[h] * SCALE_;
        float r0 = (v0 * c0 - v2 * s0) * gn;
        float r1 = (v1 * c1 - v3 * s1) * gn;
        float r2 = (v2 * c0 + v0 * s0) * gn;
        float r3 = (v3 * c1 + v1 * s1) * gn;
        size_t base = ((size_t)(b * H_ + h) * T_ + t) * HD_;
        __nv_bfloat16 hh, ll;
        bsplit(r0, hh, ll); g_qh[base + lane] = hh;      g_ql[base + lane] = ll;
        bsplit(r1, hh, ll); g_qh[base + lane + 32] = hh; g_ql[base + lane + 32] = ll;
        bsplit(r2, hh, ll); g_qh[base + lane + 64] = hh; g_ql[base + lane + 64] = ll;
        bsplit(r3, hh, ll); g_qh[base + lane + 96] = hh; g_ql[base + lane + 96] = ll;
    } else if (gwarp < NQ + NK) {
        int w = gwarp - NQ;
        int g = w % HKV_;
        int bt = w / HKV_;
        int t = bt % T_, b = bt / T_;
        const float* src = g_qkv + (size_t)bt * QKVN_ + C_ + g * HD_;
        float v0 = src[lane], v1 = src[lane + 32], v2 = src[lane + 64], v3 = src[lane + 96];
        float ss = v0 * v0 + v1 * v1 + v2 * v2 + v3 * v3;
#pragma unroll
        for (int o = 16; o; o >>= 1) ss += __shfl_xor_sync(0xffffffffu, ss, o);
        float sc = rsqrtf(ss * (1.0f / HD_) + EPS_);
        v0 *= sc; v1 *= sc; v2 *= sc; v3 *= sc;
        float c0 = g_cos[t * 64 + lane],      s0 = g_sin[t * 64 + lane];
        float c1 = g_cos[t * 64 + 32 + lane], s1 = g_sin[t * 64 + 32 + lane];
        float r0 = v0 * c0 - v2 * s0;
        float r1 = v1 * c1 - v3 * s1;
        float r2 = v2 * c0 + v0 * s0;
        float r3 = v3 * c1 + v1 * s1;
        size_t base = ((size_t)(b * HKV_ + g) * T_ + t) * HD_;
        __nv_bfloat16 hh, ll;
        bsplit(r0, hh, ll); g_kh[base + lane] = hh;      g_kl[base + lane] = ll;
        bsplit(r1, hh, ll); g_kh[base + lane + 32] = hh; g_kl[base + lane + 32] = ll;
        bsplit(r2, hh, ll); g_kh[base + lane + 64] = hh; g_kl[base + lane + 64] = ll;
        bsplit(r3, hh, ll); g_kh[base + lane + 96] = hh; g_kl[base + lane + 96] = ll;
    }
}

// ---------------- V transpose + split: [t][hd] f32 -> [hd][t] bf16 hi/lo -----------
__global__ void __launch_bounds__(256) k_vt() {
    __shared__ float vs[64][129];
    int t0 = blockIdx.x * 64;
    int g = blockIdx.y, b = blockIdx.z;
    int tid = threadIdx.x;
#pragma unroll
    for (int s = 0; s < 8; s++) {
        int c = tid + s * 256;
        int r = c >> 5, q = (c & 31) * 4;
        const float* src = g_qkv + (size_t)(b * T_ + t0 + r) * QKVN_ + C_ + KVD_ + g * HD_ + q;
        float4 v = *(const float4*)src;
        vs[r][q] = v.x; vs[r][q + 1] = v.y; vs[r][q + 2] = v.z; vs[r][q + 3] = v.w;
    }
    __syncthreads();
    int hd = tid >> 1, half = tid & 1;
    __align__(16) __nv_bfloat16 hb[32], lb[32];
#pragma unroll
    for (int j = 0; j < 32; j++)
        bsplit(vs[half * 32 + j][hd], hb[j], lb[j]);
    size_t dst = ((size_t)(b * HKV_ + g) * HD_ + hd) * T_ + t0 + half * 32;
#pragma unroll
    for (int q = 0; q < 4; q++) {
        *(uint4*)(g_vth + dst + q * 8) = *(uint4*)(hb + q * 8);
        *(uint4*)(g_vtl + dst + q * 8) = *(uint4*)(lb + q * 8);
    }
}

// ---------------- tensor-core causal flash attention, BM=128, dbuf KV --------------
#define FQSTR 272
#define FVSTR 144
#define FQ_TILE (128 * FQSTR)      // 34816
#define FK_TILE (64 * FQSTR)       // 17408
#define FV_TILE (128 * FVSTR)      // 18432
#define OFF_QH 0
#define OFF_QL FQ_TILE
#define OFF_STG (2 * FQ_TILE)                 // 69632
#define KV_STG (2 * FK_TILE + 2 * FV_TILE)    // 71680
#define FT_SMEM (OFF_STG + 2 * KV_STG)        // 212992

__global__ void __launch_bounds__(256) k_flash_t() {
    extern __shared__ char smf[];
    uint32_t sb = smem_u32(smf);
    int tid = threadIdx.x, wid = tid >> 5, lane = tid & 31;
    int qt = gridDim.x - 1 - blockIdx.x;           // longest blocks first
    int h = blockIdx.y, b = blockIdx.z, g = h >> 2;
    int q0 = qt * 128;

    const __nv_bfloat16* Qh = g_qh + ((size_t)(b * H_ + h) * T_ + q0) * HD_;
    const __nv_bfloat16* Ql = g_ql + ((size_t)(b * H_ + h) * T_ + q0) * HD_;
    const __nv_bfloat16* Kh = g_kh + (size_t)(b * HKV_ + g) * T_ * HD_;
    const __nv_bfloat16* Kl = g_kl + (size_t)(b * HKV_ + g) * T_ * HD_;
    const __nv_bfloat16* Vh = g_vth + (size_t)(b * HKV_ + g) * HD_ * T_;
    const __nv_bfloat16* Vl = g_vtl + (size_t)(b * HKV_ + g) * HD_ * T_;

    // Q tiles -> smem (once): 128 rows x 16 chunks x 2 = 4096 chunks
#pragma unroll
    for (int s = 0; s < 16; s++) {
        int c = tid + s * 256;
        int t = c >> 11, cw = c & 2047;
        int r = cw >> 4, q = cw & 15;
        const __nv_bfloat16* src = (t ? Ql : Qh) + (size_t)r * HD_ + q * 8;
        cpa16(sb + (t ? OFF_QL : OFF_QH) + r * FQSTR + q * 16, src);
    }
    auto load_kv = [&](int ks, int buf) {
        int k0 = ks * 64;
        uint32_t base = sb + OFF_STG + buf * KV_STG;
#pragma unroll
        for (int s = 0; s < 16; s++) {
            int c = tid + s * 256;               // 0..4095
            if (c < 2048) {                       // K hi/lo
                int t = c >> 10, cw = c & 1023;
                int r = cw >> 4, q = cw & 15;
                const __nv_bfloat16* src = (t ? Kl : Kh) + (size_t)(k0 + r) * HD_ + q * 8;
                cpa16(base + t * FK_TILE + r * FQSTR + q * 16, src);
            } else {                               // V hi/lo (transposed layout)
                int cv = c - 2048;
                int t = cv >> 10, cw = cv & 1023;
                int rv = cw >> 3, qv = cw & 7;
                const __nv_bfloat16* src = (t ? Vl : Vh) + (size_t)rv * T_ + k0 + qv * 8;
                cpa16(base + 2 * FK_TILE + t * FV_TILE + rv * FVSTR + qv * 16, src);
            }
        }
    };

    int ntiles = 2 * qt + 2;
    load_kv(0, 0);
    cpa_commit();

    float m0 = -INFINITY, m1 = -INFINITY, l0 = 0.f, l1 = 0.f;
    float oacc[16][4] = {};

    uint32_t qa = (uint32_t)(wid * 16 + (lane & 15)) * FQSTR + ((lane >> 4) << 4);
    uint32_t kb = (uint32_t)((lane & 7) + ((lane & 16) >> 1)) * FQSTR + ((lane & 8) << 1);
    uint32_t vb = (uint32_t)((lane & 7) + ((lane & 16) >> 1)) * FVSTR + ((lane & 8) << 1);

    for (int ks = 0; ks < ntiles; ks++) {
        int buf = ks & 1;
        if (ks + 1 < ntiles) {
            load_kv(ks + 1, buf ^ 1);
            cpa_commit();
            cpa_wait1();
        } else {
            cpa_wait0();
        }
        __syncthreads();

        uint32_t stg = sb + OFF_STG + buf * KV_STG;
        uint32_t pKH = stg + kb;
        uint32_t pKL = stg + FK_TILE + kb;
        uint32_t pVH = stg + 2 * FK_TILE + vb;
        uint32_t pVL = stg + 2 * FK_TILE + FV_TILE + vb;

        // ---- S = Q @ K^T (3-term split) ----
        float sacc[8][4] = {};
#pragma unroll
        for (int kc = 0; kc < 8; kc++) {
            uint32_t qh4[4], ql4[4];
            ldm_x4(qh4, sb + OFF_QH + qa + kc * 32);
            ldm_x4(ql4, sb + OFF_QL + qa + kc * 32);
#pragma unroll
            for (int pr = 0; pr < 4; pr++) {
                uint32_t kh4[4], kl4[4];
                ldm_x4(kh4, pKH + pr * 16 * FQSTR + kc * 32);
                ldm_x4(kl4, pKL + pr * 16 * FQSTR + kc * 32);
                mma_bf16(sacc[2 * pr],     qh4, kh4);
                mma_bf16(sacc[2 * pr],     qh4, kl4);
                mma_bf16(sacc[2 * pr],     ql4, kh4);
                mma_bf16(sacc[2 * pr + 1], qh4, kh4 + 2);
                mma_bf16(sacc[2 * pr + 1], qh4, kl4 + 2);
                mma_bf16(sacc[2 * pr + 1], ql4, kh4 + 2);
            }
        }

        // ---- causal mask (only tiles overlapping the diagonal) ----
        if (ks >= 2 * qt) {
            int r0g = q0 + wid * 16 + (lane >> 2);
            int cbase = ks * 64 + (lane & 3) * 2;
#pragma unroll
            for (int nt = 0; nt < 8; nt++) {
                int c0 = cbase + nt * 8;
                if (c0     > r0g)     sacc[nt][0] = -INFINITY;
                if (c0 + 1 > r0g)     sacc[nt][1] = -INFINITY;
                if (c0     > r0g + 8) sacc[nt][2] = -INFINITY;
                if (c0 + 1 > r0g + 8) sacc[nt][3] = -INFINITY;
            }
        }

        // ---- online softmax ----
        float mt0 = -INFINITY, mt1 = -INFINITY;
#pragma unroll
        for (int nt = 0; nt < 8; nt++) {
            mt0 = fmaxf(mt0, fmaxf(sacc[nt][0], sacc[nt][1]));
            mt1 = fmaxf(mt1, fmaxf(sacc[nt][2], sacc[nt][3]));
        }
        mt0 = fmaxf(mt0, __shfl_xor_sync(0xffffffffu, mt0, 1));
        mt0 = fmaxf(mt0, __shfl_xor_sync(0xffffffffu, mt0, 2));
        mt1 = fmaxf(mt1, __shfl_xor_sync(0xffffffffu, mt1, 1));
        mt1 = fmaxf(mt1, __shfl_xor_sync(0xffffffffu, mt1, 2));
        float mn0 = fmaxf(m0, mt0), mn1 = fmaxf(m1, mt1);
        float al0 = __expf(m0 - mn0), al1 = __expf(m1 - mn1);
        m0 = mn0; m1 = mn1;
        float ls0 = 0.f, ls1 = 0.f;
#pragma unroll
        for (int nt = 0; nt < 8; nt++) {
            sacc[nt][0] = __expf(sacc[nt][0] - mn0);
            sacc[nt][1] = __expf(sacc[nt][1] - mn0);
            sacc[nt][2] = __expf(sacc[nt][2] - mn1);
            sacc[nt][3] = __expf(sacc[nt][3] - mn1);
            ls0 += sacc[nt][0] + sacc[nt][1];
            ls1 += sacc[nt][2] + sacc[nt][3];
        }
        ls0 += __shfl_xor_sync(0xffffffffu, ls0, 1);
        ls0 += __shfl_xor_sync(0xffffffffu, ls0, 2);
        ls1 += __shfl_xor_sync(0xffffffffu, ls1, 1);
        ls1 += __shfl_xor_sync(0xffffffffu, ls1, 2);
        l0 = l0 * al0 + ls0;
        l1 = l1 * al1 + ls1;
#pragma unroll
        for (int nt = 0; nt < 16; nt++) {
            oacc[nt][0] *= al0; oacc[nt][1] *= al0;
            oacc[nt][2] *= al1; oacc[nt][3] *= al1;
        }

        // ---- O += P @ V (3-term split) ----
#pragma unroll
        for (int kc = 0; kc < 4; kc++) {
            uint32_t pah[4], pal[4];
            float* sA = sacc[2 * kc];
            float* sB = sacc[2 * kc + 1];
            __nv_bfloat162 t0v = __floats2bfloat162_rn(sA[0], sA[1]);
            __nv_bfloat162 t1v = __floats2bfloat162_rn(sA[2], sA[3]);
            __nv_bfloat162 t2v = __floats2bfloat162_rn(sB[0], sB[1]);
            __nv_bfloat162 t3v = __floats2bfloat162_rn(sB[2], sB[3]);
            pah[0] = *(uint32_t*)&t0v; pah[1] = *(uint32_t*)&t1v;
            pah[2] = *(uint32_t*)&t2v; pah[3] = *(uint32_t*)&t3v;
            __nv_bfloat162 u0 = __floats2bfloat162_rn(sA[0] - __bfloat162float(t0v.x), sA[1] - __bfloat162float(t0v.y));
            __nv_bfloat162 u1 = __floats2bfloat162_rn(sA[2] - __bfloat162float(t1v.x), sA[3] - __bfloat162float(t1v.y));
            __nv_bfloat162 u2 = __floats2bfloat162_rn(sB[0] - __bfloat162float(t2v.x), sB[1] - __bfloat162float(t2v.y));
            __nv_bfloat162 u3 = __floats2bfloat162_rn(sB[2] - __bfloat162float(t3v.x), sB[3] - __bfloat162float(t3v.y));
            pal[0] = *(uint32_t*)&u0; pal[1] = *(uint32_t*)&u1;
            pal[2] = *(uint32_t*)&u2; pal[3] = *(uint32_t*)&u3;
#pragma unroll
            for (int pr = 0; pr < 8; pr++) {
                uint32_t vh4[4], vl4[4];
                ldm_x4(vh4, pVH + pr * 16 * FVSTR + kc * 32);
                ldm_x4(vl4, pVL + pr * 16 * FVSTR + kc * 32);
                mma_bf16(oacc[2 * pr],     pah, vh4);
                mma_bf16(oacc[2 * pr],     pah, vl4);
                mma_bf16(oacc[2 * pr],     pal, vh4);
                mma_bf16(oacc[2 * pr + 1], pah, vh4 + 2);
                mma_bf16(oacc[2 * pr + 1], pah, vl4 + 2);
                mma_bf16(oacc[2 * pr + 1], pal, vh4 + 2);
            }
        }
        __syncthreads();
    }

    // ---- epilogue: normalize, split bf16, write GEMM-A operands ----
    float inv0 = 1.0f / l0, inv1 = 1.0f / l1;
    int r0g = q0 + wid * 16 + (lane >> 2);
    size_t base0 = ((size_t)(b * T_) + r0g) * C_ + h * HD_ + (lane & 3) * 2;
    size_t base1 = base0 + (size_t)8 * C_;
#pragma unroll
    for (int nt = 0; nt < 16; nt++) {
        float v0 = oacc[nt][0] * inv0, v1 = oacc[nt][1] * inv0;
        __nv_bfloat162 hh = __floats2bfloat162_rn(v0, v1);
        __nv_bfloat162 ll = __floats2bfloat162_rn(v0 - __bfloat162float(hh.x), v1 - __bfloat162float(hh.y));
        *(uint32_t*)(g_ah + base0 + nt * 8) = *(uint32_t*)&hh;
        *(uint32_t*)(g_al + base0 + nt * 8) = *(uint32_t*)&ll;
        v0 = oacc[nt][2] * inv1; v1 = oacc[nt][3] * inv1;
        hh = __floats2bfloat162_rn(v0, v1);
        ll = __floats2bfloat162_rn(v0 - __bfloat162float(hh.x), v1 - __bfloat162float(hh.y));
        *(uint32_t*)(g_ah + base1 + nt * 8) = *(uint32_t*)&hh;
        *(uint32_t*)(g_al + base1 + nt * 8) = *(uint32_t*)&ll;
    }
}

// ---------------- launcher ----------------------------------------------------------
extern "C" void kernel_launch(void* const* d_in, const int* in_sizes, int n_in,
                              void* d_out, int out_size) {
    (void)in_sizes; (void)n_in; (void)out_size;
    const float* x      = (const float*)d_in[0];
    const float* w_qkv  = (const float*)d_in[1];
    const float* w_proj = (const float*)d_in[2];
    const float* q_gain = (const float*)d_in[3];
    float* out = (float*)d_out;

    __nv_bfloat16 *p_ah, *p_al, *p_bh1, *p_bl1, *p_bh2, *p_bl2;
    float* p_qkv;
    cudaGetSymbolAddress((void**)&p_ah, g_ah);
    cudaGetSymbolAddress((void**)&p_al, g_al);
    cudaGetSymbolAddress((void**)&p_bh1, g_bh1);
    cudaGetSymbolAddress((void**)&p_bl1, g_bl1);
    cudaGetSymbolAddress((void**)&p_bh2, g_bh2);
    cudaGetSymbolAddress((void**)&p_bl2, g_bl2);
    cudaGetSymbolAddress((void**)&p_qkv, g_qkv);

    cudaFuncSetAttribute(k_gemm_bf16, cudaFuncAttributeMaxDynamicSharedMemorySize, GSMEM);
    cudaFuncSetAttribute(k_flash_t, cudaFuncAttributeMaxDynamicSharedMemorySize, FT_SMEM);

    k_rope<<<T_, 64>>>();
    k_rmsnorm<<<M_ROWS, 256>>>(x);

    dim3 gw1(QKVN_ / 32, C_ / 32);
    k_splitw<<<gw1, 256>>>(w_qkv, p_bh1, p_bl1, C_, QKVN_);
    dim3 gw2(C_ / 32, C_ / 32);
    k_splitw<<<gw2, 256>>>(w_proj, p_bh2, p_bl2, C_, C_);

    dim3 g1(QKVN_ / 256, M_ROWS / 128);
    k_gemm_bf16<<<g1, 256, GSMEM>>>(p_ah, p_al, p_bh1, p_bl1, p_qkv, M_ROWS, QKVN_, C_);

    int njobs = B_ * T_ * H_ + B_ * T_ * HKV_;
    k_qkpost<<<njobs / 8, 256>>>(q_gain);
    dim3 gv(T_ / 64, HKV_, B_);
    k_vt<<<gv, 256>>>();

    dim3 gf(T_ / 128, H_, B_);
    k_flash_t<<<gf, 256, FT_SMEM>>>();

    dim3 g2(C_ / 256, M_ROWS / 128);
    k_gemm_bf16<<<g2, 256, GSMEM>>>(p_ah, p_al, p_bh2, p_bl2, out, M_ROWS, C_, C_);
}

// round 7
// speedup vs baseline: 1.0668x; 1.0668x over previous
#include <cuda_runtime.h>
#include <cuda_bf16.h>
#include <math.h>
#include <stdint.h>

#define B_    2
#define T_    2048
#define C_    2048
#define H_    16
#define HKV_  4
#define HD_   128
#define KVD_  512
#define QKVN_ 3072
#define EPS_  1.1920929e-07f
#define M_ROWS (B_ * T_)     // 4096
#define SCALE_ 0.08838834764831845f

// ---------------- scratch -----------------------------------------------------
__device__ __nv_bfloat16 g_ah[(size_t)M_ROWS * C_];
__device__ __nv_bfloat16 g_al[(size_t)M_ROWS * C_];
__device__ __nv_bfloat16 g_bh1[(size_t)QKVN_ * C_];
__device__ __nv_bfloat16 g_bl1[(size_t)QKVN_ * C_];
__device__ __nv_bfloat16 g_bh2[(size_t)C_ * C_];
__device__ __nv_bfloat16 g_bl2[(size_t)C_ * C_];
__device__ float g_qkv[(size_t)M_ROWS * QKVN_];
__device__ __nv_bfloat16 g_qh[(size_t)B_ * H_ * T_ * HD_];
__device__ __nv_bfloat16 g_ql[(size_t)B_ * H_ * T_ * HD_];
__device__ __nv_bfloat16 g_kh[(size_t)B_ * HKV_ * T_ * HD_];
__device__ __nv_bfloat16 g_kl[(size_t)B_ * HKV_ * T_ * HD_];
__device__ __nv_bfloat16 g_vth[(size_t)B_ * HKV_ * HD_ * T_];
__device__ __nv_bfloat16 g_vtl[(size_t)B_ * HKV_ * HD_ * T_];
__device__ float g_cos[T_ * 64];
__device__ float g_sin[T_ * 64];

// ---------------- PTX helpers ---------------------------------------------------
__device__ __forceinline__ uint32_t smem_u32(const void* p) {
    uint32_t a;
    asm("{ .reg .u64 t; cvta.to.shared.u64 t, %1; cvt.u32.u64 %0, t; }" : "=r"(a) : "l"(p));
    return a;
}
__device__ __forceinline__ void cpa16(uint32_t dst, const void* src) {
    asm volatile("cp.async.cg.shared.global [%0], [%1], 16;" :: "r"(dst), "l"(src) : "memory");
}
__device__ __forceinline__ void cpa_commit() { asm volatile("cp.async.commit_group;" ::: "memory"); }
__device__ __forceinline__ void cpa_wait0()  { asm volatile("cp.async.wait_group 0;" ::: "memory"); }
__device__ __forceinline__ void cpa_wait1()  { asm volatile("cp.async.wait_group 1;" ::: "memory"); }

__device__ __forceinline__ void ldm_x4(uint32_t* r, uint32_t addr) {
    asm volatile("ldmatrix.sync.aligned.m8n8.x4.shared.b16 {%0,%1,%2,%3}, [%4];"
                 : "=r"(r[0]), "=r"(r[1]), "=r"(r[2]), "=r"(r[3]) : "r"(addr));
}
__device__ __forceinline__ void mma_bf16(float* c, const uint32_t* a, const uint32_t* b) {
    asm volatile(
        "mma.sync.aligned.m16n8k16.row.col.f32.bf16.bf16.f32 "
        "{%0,%1,%2,%3},{%4,%5,%6,%7},{%8,%9},{%0,%1,%2,%3};"
        : "+f"(c[0]), "+f"(c[1]), "+f"(c[2]), "+f"(c[3])
        : "r"(a[0]), "r"(a[1]), "r"(a[2]), "r"(a[3]), "r"(b[0]), "r"(b[1]));
}
__device__ __forceinline__ void bsplit(float v, __nv_bfloat16& h, __nv_bfloat16& l) {
    h = __float2bfloat16(v);
    l = __float2bfloat16(v - __bfloat162float(h));
}

// ---------------- RoPE tables ---------------------------------------------------
__global__ void k_rope() {
    int t = blockIdx.x;
    int j = threadIdx.x;
    float invf = 1.0f / powf(10000.0f, (2.0f * (float)j) / 128.0f);
    float ang = (float)t * invf;
    g_cos[t * 64 + j] = (float)cos((double)ang);
    g_sin[t * 64 + j] = (float)sin((double)ang);
}

// ---------------- input RMSNorm -> bf16 hi/lo split -------------------------------
__global__ void __launch_bounds__(256) k_rmsnorm(const float* __restrict__ x) {
    int row = blockIdx.x;
    const float* xr = x + (size_t)row * C_;
    float ss = 0.f;
    for (int i = threadIdx.x; i < C_; i += 256) { float v = xr[i]; ss = fmaf(v, v, ss); }
    __shared__ float sh[8];
    int lane = threadIdx.x & 31, wid = threadIdx.x >> 5;
#pragma unroll
    for (int o = 16; o; o >>= 1) ss += __shfl_xor_sync(0xffffffffu, ss, o);
    if (lane == 0) sh[wid] = ss;
    __syncthreads();
    float tot = (threadIdx.x < 8) ? sh[threadIdx.x] : 0.f;
    if (wid == 0) {
#pragma unroll
        for (int o = 16; o; o >>= 1) tot += __shfl_xor_sync(0xffffffffu, tot, o);
    }
    __shared__ float sb;
    if (threadIdx.x == 0) sb = tot;
    __syncthreads();
    float sc = rsqrtf(sb * (1.0f / C_) + EPS_);
    for (int i = threadIdx.x; i < C_; i += 256) {
        float v = xr[i] * sc;
        __nv_bfloat16 h, l;
        bsplit(v, h, l);
        g_ah[(size_t)row * C_ + i] = h;
        g_al[(size_t)row * C_ + i] = l;
    }
}

// ---------------- W[K,N] -> W^T[N,K] bf16 hi/lo split -----------------------------
__global__ void __launch_bounds__(256) k_splitw(const float* __restrict__ W,
                                                __nv_bfloat16* __restrict__ Bh,
                                                __nv_bfloat16* __restrict__ Bl,
                                                int K, int N) {
    __shared__ float ts[32][33];
    int nb = blockIdx.x * 32, kb = blockIdx.y * 32;
    int tx = threadIdx.x & 31, ty = threadIdx.x >> 5;
#pragma unroll
    for (int r = ty; r < 32; r += 8)
        ts[r][tx] = W[(size_t)(kb + r) * N + nb + tx];
    __syncthreads();
#pragma unroll
    for (int r = ty; r < 32; r += 8) {
        float v = ts[tx][r];
        __nv_bfloat16 h, l;
        bsplit(v, h, l);
        size_t o = (size_t)(nb + r) * K + kb + tx;
        Bh[o] = h;
        Bl[o] = l;
    }
}

// ---------------- bf16-split mma.sync GEMM: 128x128 block, 64x64 warp tiles --------
// 4 warps (2x2), 128 threads. Same smem footprint as R5 -> 2 blocks/SM.
#define TSTRIDE 80
#define TILE_BYTES (128 * TSTRIDE)
#define STAGE_BYTES (4 * TILE_BYTES)
#define GSMEM (2 * STAGE_BYTES)

__global__ void __launch_bounds__(128) k_gemm_bf16(const __nv_bfloat16* __restrict__ Ah,
                                                   const __nv_bfloat16* __restrict__ Al,
                                                   const __nv_bfloat16* __restrict__ Bh,
                                                   const __nv_bfloat16* __restrict__ Bl,
                                                   float* __restrict__ Cm,
                                                   int M, int N, int K) {
    extern __shared__ char smraw[];
    uint32_t sb = smem_u32(smraw);

    int tid = threadIdx.x;
    int wid = tid >> 5, lane = tid & 31;
    int warp_m = wid & 1, warp_n = wid >> 1;      // 2 x 2 grid of 64x64
    int m0 = blockIdx.y * 128, n0 = blockIdx.x * 128;
    int NIT = K >> 5;

    const __nv_bfloat16* bases[4] = {
        Ah + (size_t)m0 * K, Al + (size_t)m0 * K,
        Bh + (size_t)n0 * K, Bl + (size_t)n0 * K };

    auto load_stage = [&](int it, int buf) {
        int k0 = it << 5;
        uint32_t dst0 = sb + buf * STAGE_BYTES;
#pragma unroll
        for (int s = 0; s < 16; s++) {
            int c = tid + s * 128;                // 0..2047
            int t = c >> 9;
            int cw = c & 511;
            int row = cw >> 2, q = cw & 3;
            const __nv_bfloat16* src = bases[t] + (size_t)row * K + k0 + q * 8;
            cpa16(dst0 + t * TILE_BYTES + row * TSTRIDE + q * 16, src);
        }
    };

    float acc[4][8][4] = {};
    uint32_t a_off = (uint32_t)(warp_m * 64 + (lane & 15)) * TSTRIDE + ((lane >> 4) << 4);
    uint32_t b_off = (uint32_t)(warp_n * 64 + (lane & 7) + ((lane & 16) >> 1)) * TSTRIDE
                   + ((lane & 8) << 1);

    load_stage(0, 0);
    cpa_commit();

    for (int it = 0; it < NIT; it++) {
        int buf = it & 1;
        if (it + 1 < NIT) {
            load_stage(it + 1, buf ^ 1);
            cpa_commit();
            cpa_wait1();
        } else {
            cpa_wait0();
        }
        __syncthreads();

        uint32_t stg = sb + buf * STAGE_BYTES;
        uint32_t aH = stg + a_off;
        uint32_t aL = stg + TILE_BYTES + a_off;
        uint32_t bH = stg + 2 * TILE_BYTES + b_off;
        uint32_t bL = stg + 3 * TILE_BYTES + b_off;

#pragma unroll
        for (int ks = 0; ks < 2; ks++) {
            uint32_t ko = ks * 32;
            uint32_t ah[4][4], al[4][4];
#pragma unroll
            for (int mt = 0; mt < 4; mt++) {
                ldm_x4(ah[mt], aH + ko + mt * 16 * TSTRIDE);
                ldm_x4(al[mt], aL + ko + mt * 16 * TSTRIDE);
            }
#pragma unroll
            for (int bp = 0; bp < 4; bp++) {
                uint32_t bh4[4], bl4[4];
                ldm_x4(bh4, bH + ko + bp * 16 * TSTRIDE);
                ldm_x4(bl4, bL + ko + bp * 16 * TSTRIDE);
#pragma unroll
                for (int mt = 0; mt < 4; mt++) {
                    mma_bf16(acc[mt][2 * bp],     ah[mt], bh4);
                    mma_bf16(acc[mt][2 * bp],     ah[mt], bl4);
                    mma_bf16(acc[mt][2 * bp],     al[mt], bh4);
                    mma_bf16(acc[mt][2 * bp + 1], ah[mt], bh4 + 2);
                    mma_bf16(acc[mt][2 * bp + 1], ah[mt], bl4 + 2);
                    mma_bf16(acc[mt][2 * bp + 1], al[mt], bh4 + 2);
                }
            }
        }
        __syncthreads();
    }

    int gid = lane >> 2, tg = lane & 3;
#pragma unroll
    for (int mt = 0; mt < 4; mt++) {
#pragma unroll
        for (int nt = 0; nt < 8; nt++) {
            int row = m0 + warp_m * 64 + mt * 16 + gid;
            int col = n0 + warp_n * 64 + nt * 8 + tg * 2;
            *(float2*)(Cm + (size_t)row * N + col) =
                make_float2(acc[mt][nt][0], acc[mt][nt][1]);
            *(float2*)(Cm + (size_t)(row + 8) * N + col) =
                make_float2(acc[mt][nt][2], acc[mt][nt][3]);
        }
    }
}

// ---------------- Q/K rmsnorm + RoPE + gain*scale -> bf16 hi/lo ---------------------
__global__ void __launch_bounds__(256) k_qkpost(const float* __restrict__ qg) {
    int gwarp = (blockIdx.x * 256 + threadIdx.x) >> 5;
    int lane = threadIdx.x & 31;
    const int NQ = B_ * T_ * H_;
    const int NK = B_ * T_ * HKV_;
    if (gwarp < NQ) {
        int h = gwarp % H_;
        int bt = gwarp / H_;
        int t = bt % T_, b = bt / T_;
        const float* src = g_qkv + (size_t)bt * QKVN_ + h * HD_;
        float v0 = src[lane], v1 = src[lane + 32], v2 = src[lane + 64], v3 = src[lane + 96];
        float ss = v0 * v0 + v1 * v1 + v2 * v2 + v3 * v3;
#pragma unroll
        for (int o = 16; o; o >>= 1) ss += __shfl_xor_sync(0xffffffffu, ss, o);
        float sc = rsqrtf(ss * (1.0f / HD_) + EPS_);
        v0 *= sc; v1 *= sc; v2 *= sc; v3 *= sc;
        float c0 = g_cos[t * 64 + lane],      s0 = g_sin[t * 64 + lane];
        float c1 = g_cos[t * 64 + 32 + lane], s1 = g_sin[t * 64 + 32 + lane];
        float gn = qg[h] * SCALE_;
        float r0 = (v0 * c0 - v2 * s0) * gn;
        float r1 = (v1 * c1 - v3 * s1) * gn;
        float r2 = (v2 * c0 + v0 * s0) * gn;
        float r3 = (v3 * c1 + v1 * s1) * gn;
        size_t base = ((size_t)(b * H_ + h) * T_ + t) * HD_;
        __nv_bfloat16 hh, ll;
        bsplit(r0, hh, ll); g_qh[base + lane] = hh;      g_ql[base + lane] = ll;
        bsplit(r1, hh, ll); g_qh[base + lane + 32] = hh; g_ql[base + lane + 32] = ll;
        bsplit(r2, hh, ll); g_qh[base + lane + 64] = hh; g_ql[base + lane + 64] = ll;
        bsplit(r3, hh, ll); g_qh[base + lane + 96] = hh; g_ql[base + lane + 96] = ll;
    } else if (gwarp < NQ + NK) {
        int w = gwarp - NQ;
        int g = w % HKV_;
        int bt = w / HKV_;
        int t = bt % T_, b = bt / T_;
        const float* src = g_qkv + (size_t)bt * QKVN_ + C_ + g * HD_;
        float v0 = src[lane], v1 = src[lane + 32], v2 = src[lane + 64], v3 = src[lane + 96];
        float ss = v0 * v0 + v1 * v1 + v2 * v2 + v3 * v3;
#pragma unroll
        for (int o = 16; o; o >>= 1) ss += __shfl_xor_sync(0xffffffffu, ss, o);
        float sc = rsqrtf(ss * (1.0f / HD_) + EPS_);
        v0 *= sc; v1 *= sc; v2 *= sc; v3 *= sc;
        float c0 = g_cos[t * 64 + lane],      s0 = g_sin[t * 64 + lane];
        float c1 = g_cos[t * 64 + 32 + lane], s1 = g_sin[t * 64 + 32 + lane];
        float r0 = v0 * c0 - v2 * s0;
        float r1 = v1 * c1 - v3 * s1;
        float r2 = v2 * c0 + v0 * s0;
        float r3 = v3 * c1 + v1 * s1;
        size_t base = ((size_t)(b * HKV_ + g) * T_ + t) * HD_;
        __nv_bfloat16 hh, ll;
        bsplit(r0, hh, ll); g_kh[base + lane] = hh;      g_kl[base + lane] = ll;
        bsplit(r1, hh, ll); g_kh[base + lane + 32] = hh; g_kl[base + lane + 32] = ll;
        bsplit(r2, hh, ll); g_kh[base + lane + 64] = hh; g_kl[base + lane + 64] = ll;
        bsplit(r3, hh, ll); g_kh[base + lane + 96] = hh; g_kl[base + lane + 96] = ll;
    }
}

// ---------------- V transpose + split: [t][hd] f32 -> [hd][t] bf16 hi/lo -----------
__global__ void __launch_bounds__(256) k_vt() {
    __shared__ float vs[64][129];
    int t0 = blockIdx.x * 64;
    int g = blockIdx.y, b = blockIdx.z;
    int tid = threadIdx.x;
#pragma unroll
    for (int s = 0; s < 8; s++) {
        int c = tid + s * 256;
        int r = c >> 5, q = (c & 31) * 4;
        const float* src = g_qkv + (size_t)(b * T_ + t0 + r) * QKVN_ + C_ + KVD_ + g * HD_ + q;
        float4 v = *(const float4*)src;
        vs[r][q] = v.x; vs[r][q + 1] = v.y; vs[r][q + 2] = v.z; vs[r][q + 3] = v.w;
    }
    __syncthreads();
    int hd = tid >> 1, half = tid & 1;
    __align__(16) __nv_bfloat16 hb[32], lb[32];
#pragma unroll
    for (int j = 0; j < 32; j++)
        bsplit(vs[half * 32 + j][hd], hb[j], lb[j]);
    size_t dst = ((size_t)(b * HKV_ + g) * HD_ + hd) * T_ + t0 + half * 32;
#pragma unroll
    for (int q = 0; q < 4; q++) {
        *(uint4*)(g_vth + dst + q * 8) = *(uint4*)(hb + q * 8);
        *(uint4*)(g_vtl + dst + q * 8) = *(uint4*)(lb + q * 8);
    }
}

// ---------------- tensor-core causal flash attention (R5 config, desc order) --------
#define FQSTR 272
#define FVSTR 144
#define OFF_QH 0
#define OFF_QL 17408
#define OFF_KH 34816
#define OFF_KL 52224
#define OFF_VH 69632
#define OFF_VL 88064
#define FT_SMEM 106496

__global__ void __launch_bounds__(128) k_flash_t() {
    extern __shared__ char smf[];
    uint32_t sb = smem_u32(smf);
    int tid = threadIdx.x, wid = tid >> 5, lane = tid & 31;
    int qt = gridDim.x - 1 - blockIdx.x;           // longest blocks first
    int h = blockIdx.y, b = blockIdx.z, g = h >> 2;
    int q0 = qt * 64;

    const __nv_bfloat16* Qh = g_qh + ((size_t)(b * H_ + h) * T_ + q0) * HD_;
    const __nv_bfloat16* Ql = g_ql + ((size_t)(b * H_ + h) * T_ + q0) * HD_;
    const __nv_bfloat16* Kh = g_kh + (size_t)(b * HKV_ + g) * T_ * HD_;
    const __nv_bfloat16* Kl = g_kl + (size_t)(b * HKV_ + g) * T_ * HD_;
    const __nv_bfloat16* Vh = g_vth + (size_t)(b * HKV_ + g) * HD_ * T_;
    const __nv_bfloat16* Vl = g_vtl + (size_t)(b * HKV_ + g) * HD_ * T_;

#pragma unroll
    for (int s = 0; s < 8; s++) {
        int c = tid + s * 128;
        int r = c >> 4, q = c & 15;
        cpa16(sb + OFF_QH + r * FQSTR + q * 16, Qh + (size_t)r * HD_ + q * 8);
        cpa16(sb + OFF_QL + r * FQSTR + q * 16, Ql + (size_t)r * HD_ + q * 8);
    }
    auto load_kv = [&](int ks) {
        int k0 = ks * 64;
#pragma unroll
        for (int s = 0; s < 8; s++) {
            int c = tid + s * 128;
            int r = c >> 4, q = c & 15;
            cpa16(sb + OFF_KH + r * FQSTR + q * 16, Kh + (size_t)(k0 + r) * HD_ + q * 8);
            cpa16(sb + OFF_KL + r * FQSTR + q * 16, Kl + (size_t)(k0 + r) * HD_ + q * 8);
            int rv = c >> 3, qv = c & 7;
            cpa16(sb + OFF_VH + rv * FVSTR + qv * 16, Vh + (size_t)rv * T_ + k0 + qv * 8);
            cpa16(sb + OFF_VL + rv * FVSTR + qv * 16, Vl + (size_t)rv * T_ + k0 + qv * 8);
        }
    };
    load_kv(0);
    cpa_commit();
    cpa_wait0();
    __syncthreads();

    float m0 = -INFINITY, m1 = -INFINITY, l0 = 0.f, l1 = 0.f;
    float oacc[16][4] = {};

    uint32_t qa = (uint32_t)(wid * 16 + (lane & 15)) * FQSTR + ((lane >> 4) << 4);
    uint32_t kb = (uint32_t)((lane & 7) + ((lane & 16) >> 1)) * FQSTR + ((lane & 8) << 1);
    uint32_t vb = (uint32_t)((lane & 7) + ((lane & 16) >> 1)) * FVSTR + ((lane & 8) << 1);

    for (int ks = 0; ks <= qt; ks++) {
        float sacc[8][4] = {};
#pragma unroll
        for (int kc = 0; kc < 8; kc++) {
            uint32_t qh4[4], ql4[4];
            ldm_x4(qh4, sb + OFF_QH + qa + kc * 32);
            ldm_x4(ql4, sb + OFF_QL + qa + kc * 32);
#pragma unroll
            for (int pr = 0; pr < 4; pr++) {
                uint32_t kh4[4], kl4[4];
                ldm_x4(kh4, sb + OFF_KH + kb + pr * 16 * FQSTR + kc * 32);
                ldm_x4(kl4, sb + OFF_KL + kb + pr * 16 * FQSTR + kc * 32);
                mma_bf16(sacc[2 * pr],     qh4, kh4);
                mma_bf16(sacc[2 * pr],     qh4, kl4);
                mma_bf16(sacc[2 * pr],     ql4, kh4);
                mma_bf16(sacc[2 * pr + 1], qh4, kh4 + 2);
                mma_bf16(sacc[2 * pr + 1], qh4, kl4 + 2);
                mma_bf16(sacc[2 * pr + 1], ql4, kh4 + 2);
            }
        }

        if (ks == qt) {
            int r0 = wid * 16 + (lane >> 2);
#pragma unroll
            for (int nt = 0; nt < 8; nt++) {
                int c0 = nt * 8 + (lane & 3) * 2;
                if (c0     > r0)     sacc[nt][0] = -INFINITY;
                if (c0 + 1 > r0)     sacc[nt][1] = -INFINITY;
                if (c0     > r0 + 8) sacc[nt][2] = -INFINITY;
                if (c0 + 1 > r0 + 8) sacc[nt][3] = -INFINITY;
            }
        }

        float mt0 = -INFINITY, mt1 = -INFINITY;
#pragma unroll
        for (int nt = 0; nt < 8; nt++) {
            mt0 = fmaxf(mt0, fmaxf(sacc[nt][0], sacc[nt][1]));
            mt1 = fmaxf(mt1, fmaxf(sacc[nt][2], sacc[nt][3]));
        }
        mt0 = fmaxf(mt0, __shfl_xor_sync(0xffffffffu, mt0, 1));
        mt0 = fmaxf(mt0, __shfl_xor_sync(0xffffffffu, mt0, 2));
        mt1 = fmaxf(mt1, __shfl_xor_sync(0xffffffffu, mt1, 1));
        mt1 = fmaxf(mt1, __shfl_xor_sync(0xffffffffu, mt1, 2));
        float mn0 = fmaxf(m0, mt0), mn1 = fmaxf(m1, mt1);
        float al0 = __expf(m0 - mn0), al1 = __expf(m1 - mn1);
        m0 = mn0; m1 = mn1;
        float ls0 = 0.f, ls1 = 0.f;
#pragma unroll
        for (int nt = 0; nt < 8; nt++) {
            sacc[nt][0] = __expf(sacc[nt][0] - mn0);
            sacc[nt][1] = __expf(sacc[nt][1] - mn0);
            sacc[nt][2] = __expf(sacc[nt][2] - mn1);
            sacc[nt][3] = __expf(sacc[nt][3] - mn1);
            ls0 += sacc[nt][0] + sacc[nt][1];
            ls1 += sacc[nt][2] + sacc[nt][3];
        }
        ls0 += __shfl_xor_sync(0xffffffffu, ls0, 1);
        ls0 += __shfl_xor_sync(0xffffffffu, ls0, 2);
        ls1 += __shfl_xor_sync(0xffffffffu, ls1, 1);
        ls1 += __shfl_xor_sync(0xffffffffu, ls1, 2);
        l0 = l0 * al0 + ls0;
        l1 = l1 * al1 + ls1;
#pragma unroll
        for (int nt = 0; nt < 16; nt++) {
            oacc[nt][0] *= al0; oacc[nt][1] *= al0;
            oacc[nt][2] *= al1; oacc[nt][3] *= al1;
        }

#pragma unroll
        for (int kc = 0; kc < 4; kc++) {
            uint32_t pah[4], pal[4];
            float* sA = sacc[2 * kc];
            float* sB = sacc[2 * kc + 1];
            __nv_bfloat162 t0v = __floats2bfloat162_rn(sA[0], sA[1]);
            __nv_bfloat162 t1v = __floats2bfloat162_rn(sA[2], sA[3]);
            __nv_bfloat162 t2v = __floats2bfloat162_rn(sB[0], sB[1]);
            __nv_bfloat162 t3v = __floats2bfloat162_rn(sB[2], sB[3]);
            pah[0] = *(uint32_t*)&t0v; pah[1] = *(uint32_t*)&t1v;
            pah[2] = *(uint32_t*)&t2v; pah[3] = *(uint32_t*)&t3v;
            __nv_bfloat162 u0 = __floats2bfloat162_rn(sA[0] - __bfloat162float(t0v.x), sA[1] - __bfloat162float(t0v.y));
            __nv_bfloat162 u1 = __floats2bfloat162_rn(sA[2] - __bfloat162float(t1v.x), sA[3] - __bfloat162float(t1v.y));
            __nv_bfloat162 u2 = __floats2bfloat162_rn(sB[0] - __bfloat162float(t2v.x), sB[1] - __bfloat162float(t2v.y));
            __nv_bfloat162 u3 = __floats2bfloat162_rn(sB[2] - __bfloat162float(t3v.x), sB[3] - __bfloat162float(t3v.y));
            pal[0] = *(uint32_t*)&u0; pal[1] = *(uint32_t*)&u1;
            pal[2] = *(uint32_t*)&u2; pal[3] = *(uint32_t*)&u3;
#pragma unroll
            for (int pr = 0; pr < 8; pr++) {
                uint32_t vh4[4], vl4[4];
                ldm_x4(vh4, sb + OFF_VH + vb + pr * 16 * FVSTR + kc * 32);
                ldm_x4(vl4, sb + OFF_VL + vb + pr * 16 * FVSTR + kc * 32);
                mma_bf16(oacc[2 * pr],     pah, vh4);
                mma_bf16(oacc[2 * pr],     pah, vl4);
                mma_bf16(oacc[2 * pr],     pal, vh4);
                mma_bf16(oacc[2 * pr + 1], pah, vh4 + 2);
                mma_bf16(oacc[2 * pr + 1], pah, vl4 + 2);
                mma_bf16(oacc[2 * pr + 1], pal, vh4 + 2);
            }
        }
        __syncthreads();
        if (ks < qt) {
            load_kv(ks + 1);
            cpa_commit();
            cpa_wait0();
            __syncthreads();
        }
    }

    float inv0 = 1.0f / l0, inv1 = 1.0f / l1;
    int r0g = q0 + wid * 16 + (lane >> 2);
    size_t base0 = ((size_t)(b * T_) + r0g) * C_ + h * HD_ + (lane & 3) * 2;
    size_t base1 = base0 + (size_t)8 * C_;
#pragma unroll
    for (int nt = 0; nt < 16; nt++) {
        float v0 = oacc[nt][0] * inv0, v1 = oacc[nt][1] * inv0;
        __nv_bfloat162 hh = __floats2bfloat162_rn(v0, v1);
        __nv_bfloat162 ll = __floats2bfloat162_rn(v0 - __bfloat162float(hh.x), v1 - __bfloat162float(hh.y));
        *(uint32_t*)(g_ah + base0 + nt * 8) = *(uint32_t*)&hh;
        *(uint32_t*)(g_al + base0 + nt * 8) = *(uint32_t*)&ll;
        v0 = oacc[nt][2] * inv1; v1 = oacc[nt][3] * inv1;
        hh = __floats2bfloat162_rn(v0, v1);
        ll = __floats2bfloat162_rn(v0 - __bfloat162float(hh.x), v1 - __bfloat162float(hh.y));
        *(uint32_t*)(g_ah + base1 + nt * 8) = *(uint32_t*)&hh;
        *(uint32_t*)(g_al + base1 + nt * 8) = *(uint32_t*)&ll;
    }
}

// ---------------- launcher ----------------------------------------------------------
extern "C" void kernel_launch(void* const* d_in, const int* in_sizes, int n_in,
                              void* d_out, int out_size) {
    (void)in_sizes; (void)n_in; (void)out_size;
    const float* x      = (const float*)d_in[0];
    const float* w_qkv  = (const float*)d_in[1];
    const float* w_proj = (const float*)d_in[2];
    const float* q_gain = (const float*)d_in[3];
    float* out = (float*)d_out;

    __nv_bfloat16 *p_ah, *p_al, *p_bh1, *p_bl1, *p_bh2, *p_bl2;
    float* p_qkv;
    cudaGetSymbolAddress((void**)&p_ah, g_ah);
    cudaGetSymbolAddress((void**)&p_al, g_al);
    cudaGetSymbolAddress((void**)&p_bh1, g_bh1);
    cudaGetSymbolAddress((void**)&p_bl1, g_bl1);
    cudaGetSymbolAddress((void**)&p_bh2, g_bh2);
    cudaGetSymbolAddress((void**)&p_bl2, g_bl2);
    cudaGetSymbolAddress((void**)&p_qkv, g_qkv);

    cudaFuncSetAttribute(k_gemm_bf16, cudaFuncAttributeMaxDynamicSharedMemorySize, GSMEM);
    cudaFuncSetAttribute(k_flash_t, cudaFuncAttributeMaxDynamicSharedMemorySize, FT_SMEM);

    k_rope<<<T_, 64>>>();
    k_rmsnorm<<<M_ROWS, 256>>>(x);

    dim3 gw1(QKVN_ / 32, C_ / 32);
    k_splitw<<<gw1, 256>>>(w_qkv, p_bh1, p_bl1, C_, QKVN_);
    dim3 gw2(C_ / 32, C_ / 32);
    k_splitw<<<gw2, 256>>>(w_proj, p_bh2, p_bl2, C_, C_);

    dim3 g1(QKVN_ / 128, M_ROWS / 128);
    k_gemm_bf16<<<g1, 128, GSMEM>>>(p_ah, p_al, p_bh1, p_bl1, p_qkv, M_ROWS, QKVN_, C_);

    int njobs = B_ * T_ * H_ + B_ * T_ * HKV_;
    k_qkpost<<<njobs / 8, 256>>>(q_gain);
    dim3 gv(T_ / 64, HKV_, B_);
    k_vt<<<gv, 256>>>();

    dim3 gf(T_ / 64, H_, B_);
    k_flash_t<<<gf, 128, FT_SMEM>>>();

    dim3 g2(C_ / 128, M_ROWS / 128);
    k_gemm_bf16<<<g2, 128, GSMEM>>>(p_ah, p_al, p_bh2, p_bl2, out, M_ROWS, C_, C_);
}

// round 8
// speedup vs baseline: 1.6377x; 1.5352x over previous
#include <cuda_runtime.h>
#include <cuda_bf16.h>
#include <cuda_fp16.h>
#include <math.h>
#include <stdint.h>

#define B_    2
#define T_    2048
#define C_    2048
#define H_    16
#define HKV_  4
#define HD_   128
#define KVD_  512
#define QKVN_ 3072
#define EPS_  1.1920929e-07f
#define M_ROWS (B_ * T_)     // 4096
#define SCALE_ 0.08838834764831845f

// ---------------- scratch -----------------------------------------------------
__device__ __half g_a16[(size_t)M_ROWS * C_];        // GEMM A (rmsnorm(x), later attn out)
__device__ __half g_b16_1[(size_t)QKVN_ * C_];       // w_qkv^T fp16 [N,K]
__device__ __half g_b16_2[(size_t)C_ * C_];          // w_proj^T fp16 [N,K]
__device__ float g_qkv[(size_t)M_ROWS * QKVN_];
__device__ __nv_bfloat16 g_qh[(size_t)B_ * H_ * T_ * HD_];
__device__ __nv_bfloat16 g_ql[(size_t)B_ * H_ * T_ * HD_];
__device__ __nv_bfloat16 g_kh[(size_t)B_ * HKV_ * T_ * HD_];
__device__ __nv_bfloat16 g_kl[(size_t)B_ * HKV_ * T_ * HD_];
__device__ __nv_bfloat16 g_vth[(size_t)B_ * HKV_ * HD_ * T_];
__device__ __nv_bfloat16 g_vtl[(size_t)B_ * HKV_ * HD_ * T_];
__device__ float g_cos[T_ * 64];
__device__ float g_sin[T_ * 64];

// ---------------- PTX helpers ---------------------------------------------------
__device__ __forceinline__ uint32_t smem_u32(const void* p) {
    uint32_t a;
    asm("{ .reg .u64 t; cvta.to.shared.u64 t, %1; cvt.u32.u64 %0, t; }" : "=r"(a) : "l"(p));
    return a;
}
__device__ __forceinline__ void cpa16(uint32_t dst, const void* src) {
    asm volatile("cp.async.cg.shared.global [%0], [%1], 16;" :: "r"(dst), "l"(src) : "memory");
}
__device__ __forceinline__ void cpa_commit() { asm volatile("cp.async.commit_group;" ::: "memory"); }
__device__ __forceinline__ void cpa_wait0()  { asm volatile("cp.async.wait_group 0;" ::: "memory"); }
__device__ __forceinline__ void cpa_wait1()  { asm volatile("cp.async.wait_group 1;" ::: "memory"); }

__device__ __forceinline__ void ldm_x4(uint32_t* r, uint32_t addr) {
    asm volatile("ldmatrix.sync.aligned.m8n8.x4.shared.b16 {%0,%1,%2,%3}, [%4];"
                 : "=r"(r[0]), "=r"(r[1]), "=r"(r[2]), "=r"(r[3]) : "r"(addr));
}
__device__ __forceinline__ void mma_bf16(float* c, const uint32_t* a, const uint32_t* b) {
    asm volatile(
        "mma.sync.aligned.m16n8k16.row.col.f32.bf16.bf16.f32 "
        "{%0,%1,%2,%3},{%4,%5,%6,%7},{%8,%9},{%0,%1,%2,%3};"
        : "+f"(c[0]), "+f"(c[1]), "+f"(c[2]), "+f"(c[3])
        : "r"(a[0]), "r"(a[1]), "r"(a[2]), "r"(a[3]), "r"(b[0]), "r"(b[1]));
}
__device__ __forceinline__ void mma_fp16(float* c, const uint32_t* a, const uint32_t* b) {
    asm volatile(
        "mma.sync.aligned.m16n8k16.row.col.f32.f16.f16.f32 "
        "{%0,%1,%2,%3},{%4,%5,%6,%7},{%8,%9},{%0,%1,%2,%3};"
        : "+f"(c[0]), "+f"(c[1]), "+f"(c[2]), "+f"(c[3])
        : "r"(a[0]), "r"(a[1]), "r"(a[2]), "r"(a[3]), "r"(b[0]), "r"(b[1]));
}
__device__ __forceinline__ void bsplit(float v, __nv_bfloat16& h, __nv_bfloat16& l) {
    h = __float2bfloat16(v);
    l = __float2bfloat16(v - __bfloat162float(h));
}

// ---------------- RoPE tables ---------------------------------------------------
__global__ void k_rope() {
    int t = blockIdx.x;
    int j = threadIdx.x;
    float invf = 1.0f / powf(10000.0f, (2.0f * (float)j) / 128.0f);
    float ang = (float)t * invf;
    g_cos[t * 64 + j] = (float)cos((double)ang);
    g_sin[t * 64 + j] = (float)sin((double)ang);
}

// ---------------- input RMSNorm -> fp16 -------------------------------------------
__global__ void __launch_bounds__(256) k_rmsnorm(const float* __restrict__ x) {
    int row = blockIdx.x;
    const float* xr = x + (size_t)row * C_;
    float ss = 0.f;
    for (int i = threadIdx.x; i < C_; i += 256) { float v = xr[i]; ss = fmaf(v, v, ss); }
    __shared__ float sh[8];
    int lane = threadIdx.x & 31, wid = threadIdx.x >> 5;
#pragma unroll
    for (int o = 16; o; o >>= 1) ss += __shfl_xor_sync(0xffffffffu, ss, o);
    if (lane == 0) sh[wid] = ss;
    __syncthreads();
    float tot = (threadIdx.x < 8) ? sh[threadIdx.x] : 0.f;
    if (wid == 0) {
#pragma unroll
        for (int o = 16; o; o >>= 1) tot += __shfl_xor_sync(0xffffffffu, tot, o);
    }
    __shared__ float sb;
    if (threadIdx.x == 0) sb = tot;
    __syncthreads();
    float sc = rsqrtf(sb * (1.0f / C_) + EPS_);
    for (int i = threadIdx.x; i < C_; i += 256)
        g_a16[(size_t)row * C_ + i] = __float2half_rn(xr[i] * sc);
}

// ---------------- W[K,N] -> W^T[N,K] fp16 ------------------------------------------
__global__ void __launch_bounds__(256) k_splitw(const float* __restrict__ W,
                                                __half* __restrict__ Bo,
                                                int K, int N) {
    __shared__ float ts[32][33];
    int nb = blockIdx.x * 32, kb = blockIdx.y * 32;
    int tx = threadIdx.x & 31, ty = threadIdx.x >> 5;
#pragma unroll
    for (int r = ty; r < 32; r += 8)
        ts[r][tx] = W[(size_t)(kb + r) * N + nb + tx];
    __syncthreads();
#pragma unroll
    for (int r = ty; r < 32; r += 8)
        Bo[(size_t)(nb + r) * K + kb + tx] = __float2half_rn(ts[tx][r]);
}

// ---------------- fp16 single-pass mma.sync GEMM: 128x128 block, 8 warps -----------
#define TSTRIDE 80
#define TILE_BYTES (128 * TSTRIDE)          // 10240
#define STAGE_BYTES (2 * TILE_BYTES)        // A, B
#define GSMEM (2 * STAGE_BYTES)             // 40960

__global__ void __launch_bounds__(256) k_gemm_fp16(const __half* __restrict__ A,
                                                   const __half* __restrict__ Bm,
                                                   float* __restrict__ Cm,
                                                   int M, int N, int K) {
    extern __shared__ char smraw[];
    uint32_t sb = smem_u32(smraw);

    int tid = threadIdx.x;
    int wid = tid >> 5, lane = tid & 31;
    int warp_m = wid >> 2, warp_n = wid & 3;        // 2 x 4, 64x32 tiles
    int m0 = blockIdx.y * 128, n0 = blockIdx.x * 128;
    int NIT = K >> 5;

    const __half* Abase = A + (size_t)m0 * K;
    const __half* Bbase = Bm + (size_t)n0 * K;

    auto load_stage = [&](int it, int buf) {
        int k0 = it << 5;
        uint32_t dst0 = sb + buf * STAGE_BYTES;
#pragma unroll
        for (int s = 0; s < 4; s++) {
            int c = tid + s * 256;                  // 0..1023
            int t = c >> 9;
            int cw = c & 511;
            int row = cw >> 2, q = cw & 3;
            const __half* src = (t ? Bbase : Abase) + (size_t)row * K + k0 + q * 8;
            cpa16(dst0 + t * TILE_BYTES + row * TSTRIDE + q * 16, src);
        }
    };

    float acc[4][4][4] = {};
    uint32_t a_off = (uint32_t)(warp_m * 64 + (lane & 15)) * TSTRIDE + ((lane >> 4) << 4);
    uint32_t b_off = (uint32_t)(warp_n * 32 + (lane & 7) + ((lane & 16) >> 1)) * TSTRIDE
                   + ((lane & 8) << 1);

    load_stage(0, 0);
    cpa_commit();

    for (int it = 0; it < NIT; it++) {
        int buf = it & 1;
        if (it + 1 < NIT) {
            load_stage(it + 1, buf ^ 1);
            cpa_commit();
            cpa_wait1();
        } else {
            cpa_wait0();
        }
        __syncthreads();

        uint32_t stg = sb + buf * STAGE_BYTES;
        uint32_t aP = stg + a_off;
        uint32_t bP = stg + TILE_BYTES + b_off;

#pragma unroll
        for (int ks = 0; ks < 2; ks++) {
            uint32_t ko = ks * 32;
            uint32_t af[4][4];
#pragma unroll
            for (int mt = 0; mt < 4; mt++)
                ldm_x4(af[mt], aP + ko + mt * 16 * TSTRIDE);
            uint32_t bf[4][2];
#pragma unroll
            for (int bp = 0; bp < 2; bp++) {
                uint32_t r[4];
                ldm_x4(r, bP + ko + bp * 16 * TSTRIDE);
                bf[2 * bp][0] = r[0]; bf[2 * bp][1] = r[1];
                bf[2 * bp + 1][0] = r[2]; bf[2 * bp + 1][1] = r[3];
            }
#pragma unroll
            for (int mt = 0; mt < 4; mt++)
#pragma unroll
                for (int nt = 0; nt < 4; nt++)
                    mma_fp16(acc[mt][nt], af[mt], bf[nt]);
        }
        __syncthreads();
    }

    int gid = lane >> 2, tg = lane & 3;
#pragma unroll
    for (int mt = 0; mt < 4; mt++) {
#pragma unroll
        for (int nt = 0; nt < 4; nt++) {
            int row = m0 + warp_m * 64 + mt * 16 + gid;
            int col = n0 + warp_n * 32 + nt * 8 + tg * 2;
            *(float2*)(Cm + (size_t)row * N + col) =
                make_float2(acc[mt][nt][0], acc[mt][nt][1]);
            *(float2*)(Cm + (size_t)(row + 8) * N + col) =
                make_float2(acc[mt][nt][2], acc[mt][nt][3]);
        }
    }
}

// ---------------- Q/K rmsnorm + RoPE + gain*scale -> bf16 hi/lo ---------------------
__global__ void __launch_bounds__(256) k_qkpost(const float* __restrict__ qg) {
    int gwarp = (blockIdx.x * 256 + threadIdx.x) >> 5;
    int lane = threadIdx.x & 31;
    const int NQ = B_ * T_ * H_;
    const int NK = B_ * T_ * HKV_;
    if (gwarp < NQ) {
        int h = gwarp % H_;
        int bt = gwarp / H_;
        int t = bt % T_, b = bt / T_;
        const float* src = g_qkv + (size_t)bt * QKVN_ + h * HD_;
        float v0 = src[lane], v1 = src[lane + 32], v2 = src[lane + 64], v3 = src[lane + 96];
        float ss = v0 * v0 + v1 * v1 + v2 * v2 + v3 * v3;
#pragma unroll
        for (int o = 16; o; o >>= 1) ss += __shfl_xor_sync(0xffffffffu, ss, o);
        float sc = rsqrtf(ss * (1.0f / HD_) + EPS_);
        v0 *= sc; v1 *= sc; v2 *= sc; v3 *= sc;
        float c0 = g_cos[t * 64 + lane],      s0 = g_sin[t * 64 + lane];
        float c1 = g_cos[t * 64 + 32 + lane], s1 = g_sin[t * 64 + 32 + lane];
        float gn = qg[h] * SCALE_;
        float r0 = (v0 * c0 - v2 * s0) * gn;
        float r1 = (v1 * c1 - v3 * s1) * gn;
        float r2 = (v2 * c0 + v0 * s0) * gn;
        float r3 = (v3 * c1 + v1 * s1) * gn;
        size_t base = ((size_t)(b * H_ + h) * T_ + t) * HD_;
        __nv_bfloat16 hh, ll;
        bsplit(r0, hh, ll); g_qh[base + lane] = hh;      g_ql[base + lane] = ll;
        bsplit(r1, hh, ll); g_qh[base + lane + 32] = hh; g_ql[base + lane + 32] = ll;
        bsplit(r2, hh, ll); g_qh[base + lane + 64] = hh; g_ql[base + lane + 64] = ll;
        bsplit(r3, hh, ll); g_qh[base + lane + 96] = hh; g_ql[base + lane + 96] = ll;
    } else if (gwarp < NQ + NK) {
        int w = gwarp - NQ;
        int g = w % HKV_;
        int bt = w / HKV_;
        int t = bt % T_, b = bt / T_;
        const float* src = g_qkv + (size_t)bt * QKVN_ + C_ + g * HD_;
        float v0 = src[lane], v1 = src[lane + 32], v2 = src[lane + 64], v3 = src[lane + 96];
        float ss = v0 * v0 + v1 * v1 + v2 * v2 + v3 * v3;
#pragma unroll
        for (int o = 16; o; o >>= 1) ss += __shfl_xor_sync(0xffffffffu, ss, o);
        float sc = rsqrtf(ss * (1.0f / HD_) + EPS_);
        v0 *= sc; v1 *= sc; v2 *= sc; v3 *= sc;
        float c0 = g_cos[t * 64 + lane],      s0 = g_sin[t * 64 + lane];
        float c1 = g_cos[t * 64 + 32 + lane], s1 = g_sin[t * 64 + 32 + lane];
        float r0 = v0 * c0 - v2 * s0;
        float r1 = v1 * c1 - v3 * s1;
        float r2 = v2 * c0 + v0 * s0;
        float r3 = v3 * c1 + v1 * s1;
        size_t base = ((size_t)(b * HKV_ + g) * T_ + t) * HD_;
        __nv_bfloat16 hh, ll;
        bsplit(r0, hh, ll); g_kh[base + lane] = hh;      g_kl[base + lane] = ll;
        bsplit(r1, hh, ll); g_kh[base + lane + 32] = hh; g_kl[base + lane + 32] = ll;
        bsplit(r2, hh, ll); g_kh[base + lane + 64] = hh; g_kl[base + lane + 64] = ll;
        bsplit(r3, hh, ll); g_kh[base + lane + 96] = hh; g_kl[base + lane + 96] = ll;
    }
}

// ---------------- V transpose + split: [t][hd] f32 -> [hd][t] bf16 hi/lo -----------
__global__ void __launch_bounds__(256) k_vt() {
    __shared__ float vs[64][129];
    int t0 = blockIdx.x * 64;
    int g = blockIdx.y, b = blockIdx.z;
    int tid = threadIdx.x;
#pragma unroll
    for (int s = 0; s < 8; s++) {
        int c = tid + s * 256;
        int r = c >> 5, q = (c & 31) * 4;
        const float* src = g_qkv + (size_t)(b * T_ + t0 + r) * QKVN_ + C_ + KVD_ + g * HD_ + q;
        float4 v = *(const float4*)src;
        vs[r][q] = v.x; vs[r][q + 1] = v.y; vs[r][q + 2] = v.z; vs[r][q + 3] = v.w;
    }
    __syncthreads();
    int hd = tid >> 1, half = tid & 1;
    __align__(16) __nv_bfloat16 hb[32], lb[32];
#pragma unroll
    for (int j = 0; j < 32; j++)
        bsplit(vs[half * 32 + j][hd], hb[j], lb[j]);
    size_t dst = ((size_t)(b * HKV_ + g) * HD_ + hd) * T_ + t0 + half * 32;
#pragma unroll
    for (int q = 0; q < 4; q++) {
        *(uint4*)(g_vth + dst + q * 8) = *(uint4*)(hb + q * 8);
        *(uint4*)(g_vtl + dst + q * 8) = *(uint4*)(lb + q * 8);
    }
}

// ---------------- tensor-core causal flash attention (R5 config, desc order) --------
#define FQSTR 272
#define FVSTR 144
#define OFF_QH 0
#define OFF_QL 17408
#define OFF_KH 34816
#define OFF_KL 52224
#define OFF_VH 69632
#define OFF_VL 88064
#define FT_SMEM 106496

__global__ void __launch_bounds__(128) k_flash_t() {
    extern __shared__ char smf[];
    uint32_t sb = smem_u32(smf);
    int tid = threadIdx.x, wid = tid >> 5, lane = tid & 31;
    int qt = gridDim.x - 1 - blockIdx.x;
    int h = blockIdx.y, b = blockIdx.z, g = h >> 2;
    int q0 = qt * 64;

    const __nv_bfloat16* Qh = g_qh + ((size_t)(b * H_ + h) * T_ + q0) * HD_;
    const __nv_bfloat16* Ql = g_ql + ((size_t)(b * H_ + h) * T_ + q0) * HD_;
    const __nv_bfloat16* Kh = g_kh + (size_t)(b * HKV_ + g) * T_ * HD_;
    const __nv_bfloat16* Kl = g_kl + (size_t)(b * HKV_ + g) * T_ * HD_;
    const __nv_bfloat16* Vh = g_vth + (size_t)(b * HKV_ + g) * HD_ * T_;
    const __nv_bfloat16* Vl = g_vtl + (size_t)(b * HKV_ + g) * HD_ * T_;

#pragma unroll
    for (int s = 0; s < 8; s++) {
        int c = tid + s * 128;
        int r = c >> 4, q = c & 15;
        cpa16(sb + OFF_QH + r * FQSTR + q * 16, Qh + (size_t)r * HD_ + q * 8);
        cpa16(sb + OFF_QL + r * FQSTR + q * 16, Ql + (size_t)r * HD_ + q * 8);
    }
    auto load_kv = [&](int ks) {
        int k0 = ks * 64;
#pragma unroll
        for (int s = 0; s < 8; s++) {
            int c = tid + s * 128;
            int r = c >> 4, q = c & 15;
            cpa16(sb + OFF_KH + r * FQSTR + q * 16, Kh + (size_t)(k0 + r) * HD_ + q * 8);
            cpa16(sb + OFF_KL + r * FQSTR + q * 16, Kl + (size_t)(k0 + r) * HD_ + q * 8);
            int rv = c >> 3, qv = c & 7;
            cpa16(sb + OFF_VH + rv * FVSTR + qv * 16, Vh + (size_t)rv * T_ + k0 + qv * 8);
            cpa16(sb + OFF_VL + rv * FVSTR + qv * 16, Vl + (size_t)rv * T_ + k0 + qv * 8);
        }
    };
    load_kv(0);
    cpa_commit();
    cpa_wait0();
    __syncthreads();

    float m0 = -INFINITY, m1 = -INFINITY, l0 = 0.f, l1 = 0.f;
    float oacc[16][4] = {};

    uint32_t qa = (uint32_t)(wid * 16 + (lane & 15)) * FQSTR + ((lane >> 4) << 4);
    uint32_t kb = (uint32_t)((lane & 7) + ((lane & 16) >> 1)) * FQSTR + ((lane & 8) << 1);
    uint32_t vb = (uint32_t)((lane & 7) + ((lane & 16) >> 1)) * FVSTR + ((lane & 8) << 1);

    for (int ks = 0; ks <= qt; ks++) {
        float sacc[8][4] = {};
#pragma unroll
        for (int kc = 0; kc < 8; kc++) {
            uint32_t qh4[4], ql4[4];
            ldm_x4(qh4, sb + OFF_QH + qa + kc * 32);
            ldm_x4(ql4, sb + OFF_QL + qa + kc * 32);
#pragma unroll
            for (int pr = 0; pr < 4; pr++) {
                uint32_t kh4[4], kl4[4];
                ldm_x4(kh4, sb + OFF_KH + kb + pr * 16 * FQSTR + kc * 32);
                ldm_x4(kl4, sb + OFF_KL + kb + pr * 16 * FQSTR + kc * 32);
                mma_bf16(sacc[2 * pr],     qh4, kh4);
                mma_bf16(sacc[2 * pr],     qh4, kl4);
                mma_bf16(sacc[2 * pr],     ql4, kh4);
                mma_bf16(sacc[2 * pr + 1], qh4, kh4 + 2);
                mma_bf16(sacc[2 * pr + 1], qh4, kl4 + 2);
                mma_bf16(sacc[2 * pr + 1], ql4, kh4 + 2);
            }
        }

        if (ks == qt) {
            int r0 = wid * 16 + (lane >> 2);
#pragma unroll
            for (int nt = 0; nt < 8; nt++) {
                int c0 = nt * 8 + (lane & 3) * 2;
                if (c0     > r0)     sacc[nt][0] = -INFINITY;
                if (c0 + 1 > r0)     sacc[nt][1] = -INFINITY;
                if (c0     > r0 + 8) sacc[nt][2] = -INFINITY;
                if (c0 + 1 > r0 + 8) sacc[nt][3] = -INFINITY;
            }
        }

        float mt0 = -INFINITY, mt1 = -INFINITY;
#pragma unroll
        for (int nt = 0; nt < 8; nt++) {
            mt0 = fmaxf(mt0, fmaxf(sacc[nt][0], sacc[nt][1]));
            mt1 = fmaxf(mt1, fmaxf(sacc[nt][2], sacc[nt][3]));
        }
        mt0 = fmaxf(mt0, __shfl_xor_sync(0xffffffffu, mt0, 1));
        mt0 = fmaxf(mt0, __shfl_xor_sync(0xffffffffu, mt0, 2));
        mt1 = fmaxf(mt1, __shfl_xor_sync(0xffffffffu, mt1, 1));
        mt1 = fmaxf(mt1, __shfl_xor_sync(0xffffffffu, mt1, 2));
        float mn0 = fmaxf(m0, mt0), mn1 = fmaxf(m1, mt1);
        float al0 = __expf(m0 - mn0), al1 = __expf(m1 - mn1);
        m0 = mn0; m1 = mn1;
        float ls0 = 0.f, ls1 = 0.f;
#pragma unroll
        for (int nt = 0; nt < 8; nt++) {
            sacc[nt][0] = __expf(sacc[nt][0] - mn0);
            sacc[nt][1] = __expf(sacc[nt][1] - mn0);
            sacc[nt][2] = __expf(sacc[nt][2] - mn1);
            sacc[nt][3] = __expf(sacc[nt][3] - mn1);
            ls0 += sacc[nt][0] + sacc[nt][1];
            ls1 += sacc[nt][2] + sacc[nt][3];
        }
        ls0 += __shfl_xor_sync(0xffffffffu, ls0, 1);
        ls0 += __shfl_xor_sync(0xffffffffu, ls0, 2);
        ls1 += __shfl_xor_sync(0xffffffffu, ls1, 1);
        ls1 += __shfl_xor_sync(0xffffffffu, ls1, 2);
        l0 = l0 * al0 + ls0;
        l1 = l1 * al1 + ls1;
#pragma unroll
        for (int nt = 0; nt < 16; nt++) {
            oacc[nt][0] *= al0; oacc[nt][1] *= al0;
            oacc[nt][2] *= al1; oacc[nt][3] *= al1;
        }

#pragma unroll
        for (int kc = 0; kc < 4; kc++) {
            uint32_t pah[4], pal[4];
            float* sA = sacc[2 * kc];
            float* sB = sacc[2 * kc + 1];
            __nv_bfloat162 t0v = __floats2bfloat162_rn(sA[0], sA[1]);
            __nv_bfloat162 t1v = __floats2bfloat162_rn(sA[2], sA[3]);
            __nv_bfloat162 t2v = __floats2bfloat162_rn(sB[0], sB[1]);
            __nv_bfloat162 t3v = __floats2bfloat162_rn(sB[2], sB[3]);
            pah[0] = *(uint32_t*)&t0v; pah[1] = *(uint32_t*)&t1v;
            pah[2] = *(uint32_t*)&t2v; pah[3] = *(uint32_t*)&t3v;
            __nv_bfloat162 u0 = __floats2bfloat162_rn(sA[0] - __bfloat162float(t0v.x), sA[1] - __bfloat162float(t0v.y));
            __nv_bfloat162 u1 = __floats2bfloat162_rn(sA[2] - __bfloat162float(t1v.x), sA[3] - __bfloat162float(t1v.y));
            __nv_bfloat162 u2 = __floats2bfloat162_rn(sB[0] - __bfloat162float(t2v.x), sB[1] - __bfloat162float(t2v.y));
            __nv_bfloat162 u3 = __floats2bfloat162_rn(sB[2] - __bfloat162float(t3v.x), sB[3] - __bfloat162float(t3v.y));
            pal[0] = *(uint32_t*)&u0; pal[1] = *(uint32_t*)&u1;
            pal[2] = *(uint32_t*)&u2; pal[3] = *(uint32_t*)&u3;
#pragma unroll
            for (int pr = 0; pr < 8; pr++) {
                uint32_t vh4[4], vl4[4];
                ldm_x4(vh4, sb + OFF_VH + vb + pr * 16 * FVSTR + kc * 32);
                ldm_x4(vl4, sb + OFF_VL + vb + pr * 16 * FVSTR + kc * 32);
                mma_bf16(oacc[2 * pr],     pah, vh4);
                mma_bf16(oacc[2 * pr],     pah, vl4);
                mma_bf16(oacc[2 * pr],     pal, vh4);
                mma_bf16(oacc[2 * pr + 1], pah, vh4 + 2);
                mma_bf16(oacc[2 * pr + 1], pah, vl4 + 2);
                mma_bf16(oacc[2 * pr + 1], pal, vh4 + 2);
            }
        }
        __syncthreads();
        if (ks < qt) {
            load_kv(ks + 1);
            cpa_commit();
            cpa_wait0();
            __syncthreads();
        }
    }

    // ---- epilogue: normalize, write fp16 GEMM-A operand ----
    float inv0 = 1.0f / l0, inv1 = 1.0f / l1;
    int r0g = q0 + wid * 16 + (lane >> 2);
    size_t base0 = ((size_t)(b * T_) + r0g) * C_ + h * HD_ + (lane & 3) * 2;
    size_t base1 = base0 + (size_t)8 * C_;
#pragma unroll
    for (int nt = 0; nt < 16; nt++) {
        __half2 h0 = __floats2half2_rn(oacc[nt][0] * inv0, oacc[nt][1] * inv0);
        *(uint32_t*)(g_a16 + base0 + nt * 8) = *(uint32_t*)&h0;
        __half2 h1 = __floats2half2_rn(oacc[nt][2] * inv1, oacc[nt][3] * inv1);
        *(uint32_t*)(g_a16 + base1 + nt * 8) = *(uint32_t*)&h1;
    }
}

// ---------------- launcher ----------------------------------------------------------
extern "C" void kernel_launch(void* const* d_in, const int* in_sizes, int n_in,
                              void* d_out, int out_size) {
    (void)in_sizes; (void)n_in; (void)out_size;
    const float* x      = (const float*)d_in[0];
    const float* w_qkv  = (const float*)d_in[1];
    const float* w_proj = (const float*)d_in[2];
    const float* q_gain = (const float*)d_in[3];
    float* out = (float*)d_out;

    __half *p_a16, *p_b1, *p_b2;
    float* p_qkv;
    cudaGetSymbolAddress((void**)&p_a16, g_a16);
    cudaGetSymbolAddress((void**)&p_b1, g_b16_1);
    cudaGetSymbolAddress((void**)&p_b2, g_b16_2);
    cudaGetSymbolAddress((void**)&p_qkv, g_qkv);

    cudaFuncSetAttribute(k_gemm_fp16, cudaFuncAttributeMaxDynamicSharedMemorySize, GSMEM);
    cudaFuncSetAttribute(k_flash_t, cudaFuncAttributeMaxDynamicSharedMemorySize, FT_SMEM);

    k_rope<<<T_, 64>>>();
    k_rmsnorm<<<M_ROWS, 256>>>(x);

    dim3 gw1(QKVN_ / 32, C_ / 32);
    k_splitw<<<gw1, 256>>>(w_qkv, p_b1, C_, QKVN_);
    dim3 gw2(C_ / 32, C_ / 32);
    k_splitw<<<gw2, 256>>>(w_proj, p_b2, C_, C_);

    dim3 g1(QKVN_ / 128, M_ROWS / 128);
    k_gemm_fp16<<<g1, 256, GSMEM>>>(p_a16, p_b1, p_qkv, M_ROWS, QKVN_, C_);

    int njobs = B_ * T_ * H_ + B_ * T_ * HKV_;
    k_qkpost<<<njobs / 8, 256>>>(q_gain);
    dim3 gv(T_ / 64, HKV_, B_);
    k_vt<<<gv, 256>>>();

    dim3 gf(T_ / 64, H_, B_);
    k_flash_t<<<gf, 128, FT_SMEM>>>();

    dim3 g2(C_ / 128, M_ROWS / 128);
    k_gemm_fp16<<<g2, 256, GSMEM>>>(p_a16, p_b2, out, M_ROWS, C_, C_);
}